// round 17
// baseline (speedup 1.0000x reference)
#include <cuda_runtime.h>
#include <cuda_fp16.h>

#define NCFG 21

__constant__ int c_kh[NCFG] = {74,60,49,93,76,62, 148,120,98,186,152,124,
                               235,192,156,296,241,197,373,304,248};
__constant__ int c_kw[NCFG] = {49,60,74,62,76,93, 98,120,148,124,152,186,
                               156,192,235,197,241,296,248,304,373};
__constant__ int c_off[NCFG] = {0,3626,7226,10852,16618,22394,
                                28160,42664,57064,71568,94632,117736,
                                140800,177460,214324,250984,309296,367377,
                                425689,518193,610609};
// total area = 703113 pixels; scratch: [cfg][bk(32)][pixel], half4 packed in float2
#define TOTAL_AGG 22499616
__device__ float2 g_aggh[TOTAL_AGG];   // 180 MB

// x pitched with column AND per-batch row guards.
#define PITCH  768
#define XOFF   128
#define ROWOFF 64
#define RPB    576
#define TOTROWS (8 * RPB)      // 4608
__device__ float4 g_xp[TOTROWS * PITCH];   // 56.6 MB

// Tap tables
__device__ float4 g_tyw[NCFG][224];
__device__ int4   g_tyo[NCFG][224];   // row offsets premultiplied by kw
__device__ float4 g_txw[NCFG][224];
__device__ int4   g_txo[NCFG][224];   // column offsets (float2 units)

// ---------------- packed f32x2 helpers ----------------
__device__ __forceinline__ unsigned long long f2pack(float lo, float hi) {
    unsigned long long r;
    asm("mov.b64 %0, {%1, %2};" : "=l"(r) : "f"(lo), "f"(hi));
    return r;
}
__device__ __forceinline__ void funpack(unsigned long long v, float& lo, float& hi) {
    asm("mov.b64 {%0, %1}, %2;" : "=f"(lo), "=f"(hi) : "l"(v));
}
__device__ __forceinline__ void ffma2(unsigned long long& d,
                                      unsigned long long a, unsigned long long b) {
    asm("fma.rn.f32x2 %0, %1, %2, %0;" : "+l"(d) : "l"(a), "l"(b));
}

__device__ __forceinline__ float2 pack_h4(float a, float b, float c) {
    union { float2 f; __half2 h[2]; } u;
    u.h[0] = __floats2half2_rn(a, b);
    u.h[1] = __floats2half2_rn(c, 0.0f);
    return u.f;
}

// ---------------------------------------------------------------------------
// Prep: blocks [0,4608) fill one pitched row each (data or zero guard row);
// blocks [4608,4650) compute taps. Block = 448 threads.
// ---------------------------------------------------------------------------
__global__ void __launch_bounds__(448) prep_kernel(const float* __restrict__ x) {
    if (blockIdx.x < TOTROWS) {
        const int rb = blockIdx.x;
        const int b    = rb / RPB;
        const int rloc = rb - b * RPB;
        const int r    = rloc - ROWOFF;
        const int t  = threadIdx.x;
        float4* drow = g_xp + (size_t)rb * PITCH;
        const float4 z = make_float4(0.f, 0.f, 0.f, 0.f);
        if ((unsigned)r < 448u) {
            if (t < 128)      drow[t] = z;                       // left strip
            else if (t < 320) drow[XOFF + 448 + (t - 128)] = z;  // right strip
            const float* src = x + ((size_t)(b * 448 + r) * 448 + t) * 3;
            drow[XOFF + t] = make_float4(src[0], src[1], src[2], 0.0f);
        } else {
            drow[t] = z;
            if (t < 320) drow[448 + t] = z;
        }
        return;
    }
    const int bi  = blockIdx.x - TOTROWS;   // 0..41
    const int cfg = bi % NCFG;
    const int dim = bi / NCFG;              // 0 = rows(kh), 1 = cols(kw)
    const int o   = threadIdx.x;
    if (o >= 224) return;

    const int n  = dim ? c_kw[cfg] : c_kh[cfg];
    const int kw = c_kw[cfg];

    const double ks = (n > 224) ? (double)n / 224.0 : 1.0;
    const double sf = ((double)o + 0.5) * (double)n / 224.0 - 0.5;
    const int NT = (n < 224) ? 2 : (2 * n) / 224 + 1;   // 2..4
    int lo = (int)ceil(sf - ks);

    double w[4];
    double tot = 0.0;
    for (int t = 0; t < 4; ++t) {
        double v = 0.0;
        if (t < NT) {
            int j = lo + t;
            if (j >= 0 && j < n) {
                v = 1.0 - fabs(sf - (double)j) / ks;
                if (v < 0.0) v = 0.0;
            }
        }
        w[t] = v;
        tot += v;
    }
    const double r = 1.0 / tot;

    float wf[4];
    int   of[4];
    for (int t = 0; t < 4; ++t) {
        wf[t] = (float)(w[t] * r);
        int j = lo + t;
        if (j < 0) j = 0;
        if (j > n - 1) j = n - 1;
        of[t] = dim ? j : j * kw;
    }
    if (dim == 0) {
        g_tyw[cfg][o] = make_float4(wf[0], wf[1], wf[2], wf[3]);
        g_tyo[cfg][o] = make_int4(of[0], of[1], of[2], of[3]);
    } else {
        g_txw[cfg][o] = make_float4(wf[0], wf[1], wf[2], wf[3]);
        g_txo[cfg][o] = make_int4(of[0], of[1], of[2], of[3]);
    }
}

// ---------------------------------------------------------------------------
// p3/p4 agg (unchanged from R13).
// ---------------------------------------------------------------------------
template<int S, int G, int A, int CFG0>
__global__ void __launch_bounds__(256) agg34_kernel(const float* __restrict__ wsrc) {
    const int cfg = CFG0 + blockIdx.z;
    const int kh = c_kh[cfg], kw = c_kw[cfg];
    const int area = kh * kw;
    if ((int)(blockIdx.x * 256) >= area) return;

    const int a = blockIdx.z;
    const int b = blockIdx.y;
    constexpr int G2 = G * G;

    __shared__ ulonglong2 swp2[G2];   // swp2[gh] = {(k0,k1),(k2,k3)}
    {
        const float* wb = wsrc + (size_t)(b * A + a) * 4 * G2;
        for (int t = threadIdx.x; t < 2 * G2; t += 256) {
            const int gh = t >> 1, kp = t & 1;
            const float v0 = wb[(2 * kp)     * G2 + gh];
            const float v1 = wb[(2 * kp + 1) * G2 + gh];
            ((unsigned long long*)swp2)[2 * gh + kp] = f2pack(v0, v1);
        }
    }
    __syncthreads();

    const int idx = blockIdx.x * 256 + threadIdx.x;
    if (idx >= area) return;

    const int i = idx / kw;
    const int j = idx - i * kw;
    const int p0 = (kh - S + 1) >> 1;
    const int p1 = (kw - S + 1) >> 1;
    const int ri = i - p0;
    const int cj = j - p1;

    unsigned long long acc[3][2] = {{0ull,0ull},{0ull,0ull},{0ull,0ull}};

    const float4* base = g_xp + ((size_t)(b * RPB) + ROWOFF + ri) * PITCH + XOFF + cj;

#pragma unroll 2
    for (int g = 0; g < G; ++g) {
        const float4* rowp = base + g * (S * PITCH);
        const ulonglong2* wg = swp2 + g * G;
#pragma unroll 7
        for (int h = 0; h < G; ++h) {
            const float4 xv = __ldg(rowp + h * S);
            const unsigned long long xx = f2pack(xv.x, xv.x);
            const unsigned long long xy = f2pack(xv.y, xv.y);
            const unsigned long long xz = f2pack(xv.z, xv.z);
            const ulonglong2 w2 = wg[h];
            ffma2(acc[0][0], w2.x, xx);
            ffma2(acc[1][0], w2.x, xy);
            ffma2(acc[2][0], w2.x, xz);
            ffma2(acc[0][1], w2.y, xx);
            ffma2(acc[1][1], w2.y, xy);
            ffma2(acc[2][1], w2.y, xz);
        }
    }

    float2* dst = g_aggh + (size_t)32 * c_off[cfg] + (size_t)(b * 4) * area + idx;
#pragma unroll
    for (int kp = 0; kp < 2; ++kp) {
        float c0a, c0b, c1a, c1b, c2a, c2b;
        funpack(acc[0][kp], c0a, c0b);
        funpack(acc[1][kp], c1a, c1b);
        funpack(acc[2][kp], c2a, c2b);
        __stcs(dst + (size_t)(2 * kp)     * area, pack_h4(c0a, c1a, c2a));
        __stcs(dst + (size_t)(2 * kp + 1) * area, pack_h4(c0b, c1b, c2b));
    }
}

// ---------------------------------------------------------------------------
// Specialized p5 agg (unchanged from R13).
// ---------------------------------------------------------------------------
__global__ void __launch_bounds__(256) agg5_kernel(const float* __restrict__ w5) {
    const int cfg = 12 + blockIdx.z;
    const int kh = c_kh[cfg], kw = c_kw[cfg];
    const int by = blockIdx.y;
    const int b  = by / 373;
    const int i  = by - b * 373;
    if (i >= kh) return;
    const int j0 = blockIdx.x * 256;
    if (j0 >= kw) return;

    __shared__ ulonglong2 swp2[16];
    {
        const int t = threadIdx.x;
        if (t < 32) {
            const int gh = t >> 1, kp = t & 1;
            const size_t wb = (size_t)(b * 9 + blockIdx.z) * 4;
            const float v0 = w5[(wb + 2 * kp)     * 16 + gh];
            const float v1 = w5[(wb + 2 * kp + 1) * 16 + gh];
            ((unsigned long long*)swp2)[2 * gh + kp] = f2pack(v0, v1);
        }
    }
    __syncthreads();

    const int j = j0 + threadIdx.x;
    if (j >= kw) return;

    const int p0 = (kh - 127) >> 1;
    const int p1 = (kw - 127) >> 1;
    const int ri = i - p0;
    const int cj = j - p1;

    unsigned long long acc[3][2] = {{0ull,0ull},{0ull,0ull},{0ull,0ull}};

    const float4* base = g_xp + ((size_t)(b * RPB) + ROWOFF + ri) * PITCH + XOFF + cj;

#pragma unroll
    for (int g = 0; g < 4; ++g) {
        const int r = g * 128 + ri;
        if ((unsigned)r <= 447u) {
            float4 xv[4];
#pragma unroll
            for (int h = 0; h < 4; ++h)
                xv[h] = __ldg(base + g * (128 * PITCH) + h * 128);
#pragma unroll
            for (int h = 0; h < 4; ++h) {
                const unsigned long long xx = f2pack(xv[h].x, xv[h].x);
                const unsigned long long xy = f2pack(xv[h].y, xv[h].y);
                const unsigned long long xz = f2pack(xv[h].z, xv[h].z);
                const ulonglong2 w2 = swp2[g * 4 + h];
                ffma2(acc[0][0], w2.x, xx);
                ffma2(acc[1][0], w2.x, xy);
                ffma2(acc[2][0], w2.x, xz);
                ffma2(acc[0][1], w2.y, xx);
                ffma2(acc[1][1], w2.y, xy);
                ffma2(acc[2][1], w2.y, xz);
            }
        }
    }

    const int area = kh * kw;
    float2* dst = g_aggh + (size_t)32 * c_off[cfg] + (size_t)(b * 4) * area
                + (size_t)i * kw + j;
#pragma unroll
    for (int kp = 0; kp < 2; ++kp) {
        float c0a, c0b, c1a, c1b, c2a, c2b;
        funpack(acc[0][kp], c0a, c0b);
        funpack(acc[1][kp], c1a, c1b);
        funpack(acc[2][kp], c2a, c2b);
        __stcs(dst + (size_t)(2 * kp)     * area, pack_h4(c0a, c1a, c2a));
        __stcs(dst + (size_t)(2 * kp + 1) * area, pack_h4(c0b, c1b, c2b));
    }
}

// ---------------------------------------------------------------------------
// Kernel B: resize, 8 bk slices per thread (bk + 4t, t=0..7).
// Tap math shared, 8 independent loads per tap -> high MLP, 1/8 warps.
// ---------------------------------------------------------------------------
template<int AREA, int OFF, int NR, int NC>
__device__ __forceinline__ void do_cfg8(int cfg, int bk, int ox,
                                        const float (*s_yw)[4], const int (*s_yo)[4],
                                        float A[8][3]) {
    const float2* base = g_aggh + (size_t)32 * OFF + (size_t)bk * AREA;
    const float4 xw = g_txw[cfg][ox];
    const int4   xo = g_txo[cfg][ox];
    const float xwv[4] = {xw.x, xw.y, xw.z, xw.w};
    const int   xov[4] = {xo.x, xo.y, xo.z, xo.w};
#pragma unroll
    for (int r = 0; r < NR; ++r) {
        const float wy = s_yw[cfg][r];
        const int ro = s_yo[cfg][r];
#pragma unroll
        for (int c = 0; c < NC; ++c) {
            const float w = wy * xwv[c];
            const size_t off = (size_t)ro + xov[c];
            union { float2 f; __half2 h[2]; } u[8];
#pragma unroll
            for (int t = 0; t < 8; ++t)
                u[t].f = __ldg(base + (size_t)(4 * t) * AREA + off);
#pragma unroll
            for (int t = 0; t < 8; ++t) {
                const float2 lo = __half22float2(u[t].h[0]);
                const float  hi = __low2float(u[t].h[1]);
                A[t][0] += w * lo.x;
                A[t][1] += w * lo.y;
                A[t][2] += w * hi;
            }
        }
    }
}

__global__ void resize_kernel(float* __restrict__ out) {
    const int oy = blockIdx.x;
    const int bk = blockIdx.y;          // 0..3; slices bk + 4t, t=0..7
    const int ox = threadIdx.x;

    __shared__ float s_yw[NCFG][4];
    __shared__ int   s_yo[NCFG][4];
    {
        const int t = threadIdx.x;
        if (t < NCFG * 4) {
            const int cfg = t >> 2, k = t & 3;
            s_yw[cfg][k] = ((const float*)&g_tyw[cfg][oy])[k];
            s_yo[cfg][k] = ((const int*)&g_tyo[cfg][oy])[k];
        }
    }
    __syncthreads();

    float A[8][3];
#pragma unroll
    for (int t = 0; t < 8; ++t) {
        A[t][0] = 0.f; A[t][1] = 0.f; A[t][2] = 0.f;
    }

    do_cfg8< 3626,      0, 2, 2>( 0, bk, ox, s_yw, s_yo, A);
    do_cfg8< 3600,   3626, 2, 2>( 1, bk, ox, s_yw, s_yo, A);
    do_cfg8< 3626,   7226, 2, 2>( 2, bk, ox, s_yw, s_yo, A);
    do_cfg8< 5766,  10852, 2, 2>( 3, bk, ox, s_yw, s_yo, A);
    do_cfg8< 5776,  16618, 2, 2>( 4, bk, ox, s_yw, s_yo, A);
    do_cfg8< 5766,  22394, 2, 2>( 5, bk, ox, s_yw, s_yo, A);
    do_cfg8<14504,  28160, 2, 2>( 6, bk, ox, s_yw, s_yo, A);
    do_cfg8<14400,  42664, 2, 2>( 7, bk, ox, s_yw, s_yo, A);
    do_cfg8<14504,  57064, 2, 2>( 8, bk, ox, s_yw, s_yo, A);
    do_cfg8<23064,  71568, 2, 2>( 9, bk, ox, s_yw, s_yo, A);
    do_cfg8<23104,  94632, 2, 2>(10, bk, ox, s_yw, s_yo, A);
    do_cfg8<23064, 117736, 2, 2>(11, bk, ox, s_yw, s_yo, A);
    do_cfg8<36660, 140800, 3, 2>(12, bk, ox, s_yw, s_yo, A);
    do_cfg8<36864, 177460, 2, 2>(13, bk, ox, s_yw, s_yo, A);
    do_cfg8<36660, 214324, 2, 3>(14, bk, ox, s_yw, s_yo, A);
    do_cfg8<58312, 250984, 3, 2>(15, bk, ox, s_yw, s_yo, A);
    do_cfg8<58081, 309296, 3, 3>(16, bk, ox, s_yw, s_yo, A);
    do_cfg8<58312, 367377, 2, 3>(17, bk, ox, s_yw, s_yo, A);
    do_cfg8<92504, 425689, 4, 3>(18, bk, ox, s_yw, s_yo, A);
    do_cfg8<92416, 518193, 3, 3>(19, bk, ox, s_yw, s_yo, A);
    do_cfg8<92504, 610609, 3, 4>(20, bk, ox, s_yw, s_yo, A);

#pragma unroll
    for (int t = 0; t < 8; ++t) {
        float* o = out + ((size_t)((bk + 4 * t) * 224 + oy) * 224 + ox) * 3;
        o[0] = A[t][0];  o[1] = A[t][1];  o[2] = A[t][2];
    }
}

// ---------------------------------------------------------------------------
extern "C" void kernel_launch(void* const* d_in, const int* in_sizes, int n_in,
                              void* d_out, int out_size) {
    const float* x  = (const float*)d_in[0];
    const float* w3 = (const float*)d_in[1];
    const float* w4 = (const float*)d_in[2];
    const float* w5 = (const float*)d_in[3];

    prep_kernel<<<TOTROWS + 42, 448>>>(x);

    agg34_kernel<32, 14, 6, 0><<<dim3(23, 8, 6), 256>>>(w3);
    agg34_kernel<64, 7, 6, 6><<<dim3(91, 8, 6), 256>>>(w4);
    agg5_kernel<<<dim3(2, 8 * 373, 9), 256>>>(w5);

    dim3 gridB(224, 4);   // 8 bk slices per thread
    resize_kernel<<<gridB, 224>>>((float*)d_out);
}